// round 1
// baseline (speedup 1.0000x reference)
#include <cuda_runtime.h>

// ---------------------------------------------------------------------------
// MIND loss, fully fused.
//  - separable 7x7 gaussian (gy[u]*gx[v] == exp(-(du^2+dv^2)/8)/(8*pi))
//  - M/max(M) == exp((Dmin - D)/V)  -> two passes over the 99 shifts,
//    pass A: Dmin + V (cardinal mean), pass B: accumulate |Mp - Mg|
//  - crop [7:-7] means zero-padding of the conv never matters; only the
//    circular roll wrap at abs index 384 -> 0 matters (handled at tile load)
// ---------------------------------------------------------------------------

namespace {
constexpr int HIMG = 384;
constexpr int WIMG = 384;
constexpr int BATCH = 4;
constexpr int INNER = 370;          // 384 - 2*7
constexpr int TILE_H = 32;
constexpr int TILE_W = 64;
constexpr int CH = TILE_H + 6;      // 38 conv-support rows
constexpr int RH = TILE_H + 15;     // 47 img tile rows  (halo -7..+8)
constexpr int RW = TILE_W + 15;     // 79 img tile cols
constexpr int IMG_PITCH = 81;       // odd-ish pitch -> conflict-free LDS
constexpr int ROW_PITCH = 68;       // (4r + c) banks -> conflict-free column reads
constexpr int NTHREADS = 256;
constexpr int TILES_X = (INNER + TILE_W - 1) / TILE_W;  // 6
constexpr int TILES_Y = (INNER + TILE_H - 1) / TILE_H;  // 12
constexpr int NCTAS = BATCH * TILES_X * TILES_Y;        // 288
constexpr int NUNITS = CH * (TILE_W / 8);               // 304 row-conv octet units
constexpr int SMEM_FLOATS = 2 * RH * IMG_PITCH + 2 * CH * ROW_PITCH;
constexpr int SMEM_BYTES = SMEM_FLOATS * 4;             // 51128 B

// Gaussian constants, computed exactly as numpy float64 then cast to f32.
constexpr double E98 = 0.32465246735834974;   // exp(-9/8)
constexpr double E48 = 0.60653065971263342;   // exp(-4/8)
constexpr double E18 = 0.88249690258459546;   // exp(-1/8)
constexpr double TPS = 25.132741228718345;    // 2*pi*sigma^2 = 8*pi
constexpr float GX0 = (float)E98;
constexpr float GX1 = (float)E48;
constexpr float GX2 = (float)E18;             // GX3 == 1
constexpr float GY0 = (float)(E98 / TPS);
constexpr float GY1 = (float)(E48 / TPS);
constexpr float GY2 = (float)(E18 / TPS);
constexpr float GY3 = (float)(1.0 / TPS);
}  // namespace

__device__ float g_partials[NCTAS];

// Fused diffsq + horizontal 7-tap conv. Each unit = (row r in [0,CH),
// 8-column octet j). Writes sRow[r][8j..8j+7].
__device__ __forceinline__ void row_stage(const float* __restrict__ sImg,
                                          float* __restrict__ sRow,
                                          int sx, int sy, int tid) {
#pragma unroll
  for (int uu = 0; uu < 2; uu++) {
    int u = tid + uu * NTHREADS;
    if (uu == 0 || u < NUNITS) {
      int j = u & 7;
      int r = u >> 3;
      const float* pa = sImg + (r + 4) * IMG_PITCH + (j * 8 + 4);
      const float* pb = sImg + (r + 4 - sy) * IMG_PITCH + (j * 8 + 4 - sx);
      float dsq[14];
#pragma unroll
      for (int k = 0; k < 14; k++) {
        float d = pa[k] - pb[k];
        dsq[k] = d * d;
      }
      float* pr = sRow + r * ROW_PITCH + j * 8;
#pragma unroll
      for (int c = 0; c < 8; c++) {
        float v = GX0 * dsq[c];
        v = fmaf(GX1, dsq[c + 1], v);
        v = fmaf(GX2, dsq[c + 2], v);
        v = v + dsq[c + 3];  // center tap weight == 1
        v = fmaf(GX2, dsq[c + 4], v);
        v = fmaf(GX1, dsq[c + 5], v);
        v = fmaf(GX0, dsq[c + 6], v);
        pr[c] = v;
      }
    }
  }
}

__device__ __forceinline__ void col_load(const float* __restrict__ sRow,
                                         int c, int g, float rv[14]) {
  const float* pr = sRow + (g * 8) * ROW_PITCH + c;
#pragma unroll
  for (int i = 0; i < 14; i++) rv[i] = pr[i * ROW_PITCH];
}

__device__ __forceinline__ float col7(const float rv[14], int i) {
  float v = GY0 * rv[i];
  v = fmaf(GY1, rv[i + 1], v);
  v = fmaf(GY2, rv[i + 2], v);
  v = fmaf(GY3, rv[i + 3], v);
  v = fmaf(GY2, rv[i + 4], v);
  v = fmaf(GY1, rv[i + 5], v);
  v = fmaf(GY0, rv[i + 6], v);
  return v;
}

extern "C" __global__ void __launch_bounds__(NTHREADS, 2)
mind_main(const float* __restrict__ pred, const float* __restrict__ gt) {
  extern __shared__ float smem[];
  float* sP = smem;
  float* sG = sP + RH * IMG_PITCH;
  float* sRowP = sG + RH * IMG_PITCH;
  float* sRowG = sRowP + CH * ROW_PITCH;

  const int tX = blockIdx.x, tY = blockIdx.y, b = blockIdx.z;
  const int tid = threadIdx.x;
  const float* imgP = pred + b * HIMG * WIMG;
  const float* imgG = gt + b * HIMG * WIMG;

  // Load tile + halo with circular wrap (roll semantics). Tile origin in
  // absolute coords is (7 + tY*32, 7 + tX*64); smem origin is that minus 7.
  for (int i = tid; i < RH * RW; i += NTHREADS) {
    int r = i / RW, c2 = i - r * RW;
    int gr = tY * TILE_H + r; if (gr >= HIMG) gr -= HIMG;
    int gc = tX * TILE_W + c2; if (gc >= WIMG) gc -= WIMG;
    sP[r * IMG_PITCH + c2] = imgP[gr * WIMG + gc];
    sG[r * IMG_PITCH + c2] = imgG[gr * WIMG + gc];
  }
  __syncthreads();

  const int cc = tid & 63;   // owned output column within tile
  const int gg = tid >> 6;   // owned row-group (8 rows each)

  float DminP[8], DminG[8], VP[8], VG[8];
#pragma unroll
  for (int i = 0; i < 8; i++) {
    DminP[i] = 3e38f; DminG[i] = 3e38f; VP[i] = 0.f; VG[i] = 0.f;
  }

  // ---------------- Pass A: Dmin and cardinal sum -> invV ----------------
  for (int si = 0; si < 100; si++) {
    if (si == 55) continue;              // (sx,sy) == (0,0)
    int sx = si / 10 - 5;
    int sy = si - (si / 10) * 10 - 5;
    row_stage(sP, sRowP, sx, sy, tid);
    row_stage(sG, sRowG, sx, sy, tid);
    __syncthreads();
    float rvP[14], rvG[14];
    col_load(sRowP, cc, gg, rvP);
    col_load(sRowG, cc, gg, rvG);
    bool card = ((sx == 0) & ((sy == 1) | (sy == -1))) |
                ((sy == 0) & ((sx == 1) | (sx == -1)));
#pragma unroll
    for (int i = 0; i < 8; i++) {
      float dp = col7(rvP, i);
      float dg = col7(rvG, i);
      DminP[i] = fminf(DminP[i], dp);
      DminG[i] = fminf(DminG[i], dg);
      if (card) { VP[i] += dp; VG[i] += dg; }
    }
    __syncthreads();
  }
#pragma unroll
  for (int i = 0; i < 8; i++) {
    VP[i] = 1.0f / (VP[i] * 0.25f + 1e-5f);   // invV
    VG[i] = 1.0f / (VG[i] * 0.25f + 1e-5f);
  }

  // ---------------- Pass B: accumulate |Mp - Mg| ----------------
  float acc = 0.f;
  const int px = tX * TILE_W + cc;
  const bool cOK = px < INNER;
  const int py0 = tY * TILE_H + gg * 8;
  for (int si = 0; si < 100; si++) {
    if (si == 55) continue;
    int sx = si / 10 - 5;
    int sy = si - (si / 10) * 10 - 5;
    row_stage(sP, sRowP, sx, sy, tid);
    row_stage(sG, sRowG, sx, sy, tid);
    __syncthreads();
    float rvP[14], rvG[14];
    col_load(sRowP, cc, gg, rvP);
    col_load(sRowG, cc, gg, rvG);
#pragma unroll
    for (int i = 0; i < 8; i++) {
      float dp = col7(rvP, i);
      float dg = col7(rvG, i);
      float mp = __expf((DminP[i] - dp) * VP[i]);
      float mg = __expf((DminG[i] - dg) * VG[i]);
      if (cOK && (py0 + i) < INNER) acc += fabsf(mp - mg);
    }
    __syncthreads();
  }

  // Deterministic per-CTA reduction.
#pragma unroll
  for (int o = 16; o > 0; o >>= 1) acc += __shfl_down_sync(0xffffffffu, acc, o);
  if ((tid & 31) == 0) smem[tid >> 5] = acc;  // safe: trailing sync above
  __syncthreads();
  if (tid == 0) {
    float s = 0.f;
#pragma unroll
    for (int w = 0; w < NTHREADS / 32; w++) s += smem[w];
    g_partials[(b * TILES_Y + tY) * TILES_X + tX] = s;
  }
}

extern "C" __global__ void mind_reduce(float* __restrict__ out) {
  int tid = threadIdx.x;
  float s = 0.f;
  for (int i = tid; i < NCTAS; i += 256) s += g_partials[i];
#pragma unroll
  for (int o = 16; o > 0; o >>= 1) s += __shfl_down_sync(0xffffffffu, s, o);
  __shared__ float red[8];
  if ((tid & 31) == 0) red[tid >> 5] = s;
  __syncthreads();
  if (tid == 0) {
    float t = 0.f;
#pragma unroll
    for (int w = 0; w < 8; w++) t += red[w];
    out[0] = t * (float)(1.0 / ((double)BATCH * INNER * INNER * 99.0));
  }
}

extern "C" void kernel_launch(void* const* d_in, const int* in_sizes, int n_in,
                              void* d_out, int out_size) {
  const float* pred = (const float*)d_in[0];
  const float* gt = (const float*)d_in[1];
  // Not a stream op; legal during graph capture. Called every time
  // (idempotent, deterministic).
  cudaFuncSetAttribute(mind_main, cudaFuncAttributeMaxDynamicSharedMemorySize,
                       SMEM_BYTES);
  dim3 grid(TILES_X, TILES_Y, BATCH);
  mind_main<<<grid, NTHREADS, SMEM_BYTES>>>(pred, gt);
  mind_reduce<<<1, 256>>>((float*)d_out);
}

// round 2
// speedup vs baseline: 1.1597x; 1.1597x over previous
#include <cuda_runtime.h>

// ---------------------------------------------------------------------------
// MIND loss, fully fused. R2: conflict-free smem mappings + double buffering.
//  - separable 7x7 gaussian (gy[u]*gx[v] == exp(-(du^2+dv^2)/8)/(8*pi))
//  - M/max(M) == exp((Dmin - D)/V)  -> two passes over the 99 shifts
//  - warp unit mapping 4 octets x 8 rows; IMG_PITCH=81 (17 mod 32) and
//    ROW_PITCH=67 (3 mod 32) make every row-stage LDS/STS conflict-free
//  - read-then-write double buffering: one __syncthreads per shift
// ---------------------------------------------------------------------------

namespace {
constexpr int HIMG = 384;
constexpr int WIMG = 384;
constexpr int BATCH = 4;
constexpr int INNER = 370;          // 384 - 2*7
constexpr int TILE_H = 32;
constexpr int TILE_W = 64;
constexpr int CHP = 40;             // conv-support rows, padded 38 -> 40
constexpr int RH = 49;              // img tile rows (halo -7..+8, +2 pad rows)
constexpr int RW = 79;              // img tile cols
constexpr int IMG_PITCH = 81;       // 81 mod 32 == 17 -> conflict-free loads
constexpr int ROW_PITCH = 67;       // 67 mod 32 == 3  -> conflict-free stores
constexpr int NTHREADS = 256;
constexpr int TILES_X = (INNER + TILE_W - 1) / TILE_W;  // 6
constexpr int TILES_Y = (INNER + TILE_H - 1) / TILE_H;  // 12
constexpr int NCTAS = BATCH * TILES_X * TILES_Y;        // 288
constexpr int NUNITS = CHP * 8;                         // 320 row-conv units
// smem: 2 images + 2x2 double-buffered row-conv buffers
constexpr int SMEM_FLOATS = 2 * RH * IMG_PITCH + 4 * CHP * ROW_PITCH;
constexpr int SMEM_BYTES = SMEM_FLOATS * 4;             // 74632 B

// Gaussian constants (float64 -> float32, matching numpy).
constexpr double E98 = 0.32465246735834974;   // exp(-9/8)
constexpr double E48 = 0.60653065971263342;   // exp(-4/8)
constexpr double E18 = 0.88249690258459546;   // exp(-1/8)
constexpr double TPS = 25.132741228718345;    // 2*pi*sigma^2 = 8*pi
constexpr float GX0 = (float)E98;
constexpr float GX1 = (float)E48;
constexpr float GX2 = (float)E18;             // GX3 == 1
constexpr float GY0 = (float)(E98 / TPS);
constexpr float GY1 = (float)(E48 / TPS);
constexpr float GY2 = (float)(E18 / TPS);
constexpr float GY3 = (float)(1.0 / TPS);
}  // namespace

__device__ float g_partials[NCTAS];

// Fused diffsq + horizontal 7-tap conv for one image into one buffer.
// Unit u -> group g=u>>5, lane l=u&31; octet j = 4*(g&1)+(l&3),
// row r = 8*(g>>1)+(l>>2). Warp lanes hit 32 distinct banks on every access.
__device__ __forceinline__ void row_stage(const float* __restrict__ sImg,
                                          float* __restrict__ sRow,
                                          int sx, int sy, int tid) {
#pragma unroll
  for (int uu = 0; uu < 2; uu++) {
    int u = tid + uu * NTHREADS;
    if (uu == 0 || tid < (NUNITS - NTHREADS)) {   // 320 units total
      int g = u >> 5, l = u & 31;
      int j = ((g & 1) << 2) | (l & 3);
      int r = ((g >> 1) << 3) | (l >> 2);
      const float* pa = sImg + (r + 4) * IMG_PITCH + (j * 8 + 4);
      const float* pb = pa - sy * IMG_PITCH - sx;
      float dsq[14];
#pragma unroll
      for (int k = 0; k < 14; k++) {
        float d = pa[k] - pb[k];
        dsq[k] = d * d;
      }
      float* pr = sRow + r * ROW_PITCH + j * 8;
#pragma unroll
      for (int c = 0; c < 8; c++) {
        float v = GX0 * dsq[c];
        v = fmaf(GX1, dsq[c + 1], v);
        v = fmaf(GX2, dsq[c + 2], v);
        v = v + dsq[c + 3];  // center tap weight == 1
        v = fmaf(GX2, dsq[c + 4], v);
        v = fmaf(GX1, dsq[c + 5], v);
        v = fmaf(GX0, dsq[c + 6], v);
        pr[c] = v;
      }
    }
  }
}

__device__ __forceinline__ void col_load(const float* __restrict__ sRow,
                                         int c, int g, float rv[14]) {
  const float* pr = sRow + (g * 8) * ROW_PITCH + c;
#pragma unroll
  for (int i = 0; i < 14; i++) rv[i] = pr[i * ROW_PITCH];
}

__device__ __forceinline__ float col7(const float rv[14], int i) {
  float v = GY0 * rv[i];
  v = fmaf(GY1, rv[i + 1], v);
  v = fmaf(GY2, rv[i + 2], v);
  v = fmaf(GY3, rv[i + 3], v);
  v = fmaf(GY2, rv[i + 4], v);
  v = fmaf(GY1, rv[i + 5], v);
  v = fmaf(GY0, rv[i + 6], v);
  return v;
}

__device__ __forceinline__ void decode_shift(int si, int& sx, int& sy) {
  int t = si < 55 ? si : si + 1;   // skip (0,0) at index 55
  int q = t / 10;                  // x outer, y inner (matches reference)
  sx = q - 5;
  sy = t - q * 10 - 5;
}

extern "C" __global__ void __launch_bounds__(NTHREADS, 2)
mind_main(const float* __restrict__ pred, const float* __restrict__ gt) {
  extern __shared__ float smem[];
  float* sP = smem;
  float* sG = sP + RH * IMG_PITCH;
  float* bufP[2] = {sG + RH * IMG_PITCH,
                    sG + RH * IMG_PITCH + CHP * ROW_PITCH};
  float* bufG[2] = {bufP[1] + CHP * ROW_PITCH,
                    bufP[1] + 2 * CHP * ROW_PITCH};

  const int tX = blockIdx.x, tY = blockIdx.y, b = blockIdx.z;
  const int tid = threadIdx.x;
  const float* imgP = pred + b * HIMG * WIMG;
  const float* imgG = gt + b * HIMG * WIMG;

  // Load tile + halo with circular wrap (roll semantics).
  for (int i = tid; i < RH * RW; i += NTHREADS) {
    int r = i / RW, c2 = i - r * RW;
    int gr = tY * TILE_H + r; if (gr >= HIMG) gr -= HIMG;
    int gc = tX * TILE_W + c2; if (gc >= WIMG) gc -= WIMG;
    sP[r * IMG_PITCH + c2] = imgP[gr * WIMG + gc];
    sG[r * IMG_PITCH + c2] = imgG[gr * WIMG + gc];
  }
  __syncthreads();

  const int cc = tid & 63;   // owned output column within tile
  const int gg = tid >> 6;   // owned row-group (8 rows each)

  float DminP[8], DminG[8], VP[8], VG[8];
#pragma unroll
  for (int i = 0; i < 8; i++) {
    DminP[i] = 3e38f; DminG[i] = 3e38f; VP[i] = 0.f; VG[i] = 0.f;
  }

  int sx, sy;

  // ---------------- Pass A: Dmin and cardinal sum -> invV ----------------
  decode_shift(0, sx, sy);
  row_stage(sP, bufP[0], sx, sy, tid);
  row_stage(sG, bufG[0], sx, sy, tid);
  __syncthreads();
  for (int si = 0; si < 99; si++) {
    int cur = si & 1;
    float rvP[14], rvG[14];
    col_load(bufP[cur], cc, gg, rvP);
    col_load(bufG[cur], cc, gg, rvG);
    decode_shift(si, sx, sy);
    bool card = ((sx == 0) & ((sy == 1) | (sy == -1))) |
                ((sy == 0) & ((sx == 1) | (sx == -1)));
#pragma unroll
    for (int i = 0; i < 8; i++) {
      float dp = col7(rvP, i);
      float dg = col7(rvG, i);
      DminP[i] = fminf(DminP[i], dp);
      DminG[i] = fminf(DminG[i], dg);
      if (card) { VP[i] += dp; VG[i] += dg; }
    }
    if (si + 1 < 99) {   // produce next shift into the other buffer
      int nsx, nsy;
      decode_shift(si + 1, nsx, nsy);
      row_stage(sP, bufP[cur ^ 1], nsx, nsy, tid);
      row_stage(sG, bufG[cur ^ 1], nsx, nsy, tid);
    }
    __syncthreads();
  }
#pragma unroll
  for (int i = 0; i < 8; i++) {
    VP[i] = 1.0f / (VP[i] * 0.25f + 1e-5f);   // invV
    VG[i] = 1.0f / (VG[i] * 0.25f + 1e-5f);
  }

  // ---------------- Pass B: accumulate |Mp - Mg| ----------------
  float acc = 0.f;
  const int px = tX * TILE_W + cc;
  const bool cOK = px < INNER;
  const int py0 = tY * TILE_H + gg * 8;

  decode_shift(0, sx, sy);
  row_stage(sP, bufP[0], sx, sy, tid);
  row_stage(sG, bufG[0], sx, sy, tid);
  __syncthreads();
  for (int si = 0; si < 99; si++) {
    int cur = si & 1;
    float rvP[14], rvG[14];
    col_load(bufP[cur], cc, gg, rvP);
    col_load(bufG[cur], cc, gg, rvG);
#pragma unroll
    for (int i = 0; i < 8; i++) {
      float dp = col7(rvP, i);
      float dg = col7(rvG, i);
      float mp = __expf((DminP[i] - dp) * VP[i]);
      float mg = __expf((DminG[i] - dg) * VG[i]);
      if (cOK && (py0 + i) < INNER) acc += fabsf(mp - mg);
    }
    if (si + 1 < 99) {
      int nsx, nsy;
      decode_shift(si + 1, nsx, nsy);
      row_stage(sP, bufP[cur ^ 1], nsx, nsy, tid);
      row_stage(sG, bufG[cur ^ 1], nsx, nsy, tid);
    }
    __syncthreads();
  }

  // Deterministic per-CTA reduction.
#pragma unroll
  for (int o = 16; o > 0; o >>= 1) acc += __shfl_down_sync(0xffffffffu, acc, o);
  if ((tid & 31) == 0) smem[tid >> 5] = acc;  // all passes done; safe reuse
  __syncthreads();
  if (tid == 0) {
    float s = 0.f;
#pragma unroll
    for (int w = 0; w < NTHREADS / 32; w++) s += smem[w];
    g_partials[(b * TILES_Y + tY) * TILES_X + tX] = s;
  }
}

extern "C" __global__ void mind_reduce(float* __restrict__ out) {
  int tid = threadIdx.x;
  float s = 0.f;
  for (int i = tid; i < NCTAS; i += 256) s += g_partials[i];
#pragma unroll
  for (int o = 16; o > 0; o >>= 1) s += __shfl_down_sync(0xffffffffu, s, o);
  __shared__ float red[8];
  if ((tid & 31) == 0) red[tid >> 5] = s;
  __syncthreads();
  if (tid == 0) {
    float t = 0.f;
#pragma unroll
    for (int w = 0; w < 8; w++) t += red[w];
    out[0] = t * (float)(1.0 / ((double)BATCH * INNER * INNER * 99.0));
  }
}

extern "C" void kernel_launch(void* const* d_in, const int* in_sizes, int n_in,
                              void* d_out, int out_size) {
  const float* pred = (const float*)d_in[0];
  const float* gt = (const float*)d_in[1];
  cudaFuncSetAttribute(mind_main, cudaFuncAttributeMaxDynamicSharedMemorySize,
                       SMEM_BYTES);
  dim3 grid(TILES_X, TILES_Y, BATCH);
  mind_main<<<grid, NTHREADS, SMEM_BYTES>>>(pred, gt);
  mind_reduce<<<1, 256>>>((float*)d_out);
}

// round 3
// speedup vs baseline: 1.4086x; 1.2147x over previous
#include <cuda_runtime.h>

// ---------------------------------------------------------------------------
// MIND loss, fully fused. R3: pred/gt packed into f32x2 (FFMA2) — every
// diff/square/conv op processes both images in one packed instruction.
//  - separable 7x7 gaussian (gy[u]*gx[v] == exp(-(du^2+dv^2)/8)/(8*pi))
//  - M/max(M) == exp((Dmin - D)/V)  -> two passes over the 99 shifts
//  - 64-bit smem accesses conflict-free per 16-lane phase:
//    warp mapping j=(l>>3)&3, r=l&7 with odd float2 pitches (81 / 67)
// ---------------------------------------------------------------------------

typedef unsigned long long u64;

namespace {
constexpr int HIMG = 384;
constexpr int WIMG = 384;
constexpr int BATCH = 4;
constexpr int INNER = 370;          // 384 - 2*7
constexpr int TILE_H = 32;
constexpr int TILE_W = 64;
constexpr int CHP = 40;             // conv-support rows (38 used + 2 pad)
constexpr int RH = 49;              // img tile rows (halo -4..+44 w/ shifts)
constexpr int RW = 79;              // img tile cols
constexpr int IP2 = 81;             // img pitch in float2 units (odd)
constexpr int RP2 = 67;             // row-buf pitch in float2 units (odd)
constexpr int NTHREADS = 256;
constexpr int TILES_X = (INNER + TILE_W - 1) / TILE_W;  // 6
constexpr int TILES_Y = (INNER + TILE_H - 1) / TILE_H;  // 12
constexpr int NCTAS = BATCH * TILES_X * TILES_Y;        // 288
constexpr int NUNITS = CHP * 8;                         // 320 row-conv units
constexpr int SMEM_U64 = RH * IP2 + 2 * CHP * RP2;      // img + 2 row bufs
constexpr int SMEM_BYTES = SMEM_U64 * 8;                // 74632 B

constexpr double E98 = 0.32465246735834974;   // exp(-9/8)
constexpr double E48 = 0.60653065971263342;   // exp(-4/8)
constexpr double E18 = 0.88249690258459546;   // exp(-1/8)
constexpr double TPS = 25.132741228718345;    // 8*pi
constexpr float GX0 = (float)E98;
constexpr float GX1 = (float)E48;
constexpr float GX2 = (float)E18;             // center tap == 1
constexpr float GY0 = (float)(E98 / TPS);
constexpr float GY1 = (float)(E48 / TPS);
constexpr float GY2 = (float)(E18 / TPS);
constexpr float GY3 = (float)(1.0 / TPS);
}  // namespace

__device__ float g_partials[NCTAS];

// ---- packed f32x2 helpers (sm_100+) ----
__device__ __forceinline__ u64 bc2(float x) {
  u64 r; asm("mov.b64 %0,{%1,%1};" : "=l"(r) : "f"(x)); return r;
}
__device__ __forceinline__ u64 pk2(float a, float b) {
  u64 r; asm("mov.b64 %0,{%1,%2};" : "=l"(r) : "f"(a), "f"(b)); return r;
}
__device__ __forceinline__ void up2(u64 v, float& a, float& b) {
  asm("mov.b64 {%0,%1},%2;" : "=f"(a), "=f"(b) : "l"(v));
}
__device__ __forceinline__ u64 f2sub(u64 a, u64 b) {
  u64 r; asm("sub.rn.f32x2 %0,%1,%2;" : "=l"(r) : "l"(a), "l"(b)); return r;
}
__device__ __forceinline__ u64 f2mul(u64 a, u64 b) {
  u64 r; asm("mul.rn.f32x2 %0,%1,%2;" : "=l"(r) : "l"(a), "l"(b)); return r;
}
__device__ __forceinline__ u64 f2add(u64 a, u64 b) {
  u64 r; asm("add.rn.f32x2 %0,%1,%2;" : "=l"(r) : "l"(a), "l"(b)); return r;
}
__device__ __forceinline__ u64 f2fma(u64 a, u64 b, u64 c) {
  u64 r; asm("fma.rn.f32x2 %0,%1,%2,%3;" : "=l"(r) : "l"(a), "l"(b), "l"(c));
  return r;
}

// Fused diffsq + horizontal 7-tap conv, both images packed.
// Unit u -> warp w=u>>5, lane l=u&31; octet j=((l>>3)&3)|((w&1)<<2),
// row r=(l&7)|((w>>1)<<3). Per 16-lane phase: 16 distinct bank-pairs.
__device__ __forceinline__ void row_stage(const u64* __restrict__ sImg,
                                          u64* __restrict__ sRow,
                                          int sx, int sy, int tid) {
  const u64 gx0 = bc2(GX0), gx1 = bc2(GX1), gx2 = bc2(GX2);
#pragma unroll
  for (int uu = 0; uu < 2; uu++) {
    int u = tid + uu * NTHREADS;
    if (uu == 0 || tid < (NUNITS - NTHREADS)) {
      int w = u >> 5, l = u & 31;
      int j = ((l >> 3) & 3) | ((w & 1) << 2);
      int r = (l & 7) | ((w >> 1) << 3);
      const u64* pa = sImg + (r + 4) * IP2 + (j * 8 + 4);
      const u64* pb = pa - sy * IP2 - sx;
      u64 dsq[14];
#pragma unroll
      for (int k = 0; k < 14; k++) {
        u64 d = f2sub(pa[k], pb[k]);
        dsq[k] = f2mul(d, d);
      }
      u64* pr = sRow + r * RP2 + j * 8;
#pragma unroll
      for (int c = 0; c < 8; c++) {
        u64 v = f2mul(gx0, dsq[c]);
        v = f2fma(gx1, dsq[c + 1], v);
        v = f2fma(gx2, dsq[c + 2], v);
        v = f2add(v, dsq[c + 3]);  // center tap weight == 1
        v = f2fma(gx2, dsq[c + 4], v);
        v = f2fma(gx1, dsq[c + 5], v);
        v = f2fma(gx0, dsq[c + 6], v);
        pr[c] = v;
      }
    }
  }
}

__device__ __forceinline__ void col_load(const u64* __restrict__ sRow,
                                         int c, int g, u64 rv[14]) {
  const u64* pr = sRow + (g * 8) * RP2 + c;
#pragma unroll
  for (int i = 0; i < 14; i++) rv[i] = pr[i * RP2];
}

__device__ __forceinline__ u64 col7(const u64 rv[14], int i,
                                    u64 gy0, u64 gy1, u64 gy2, u64 gy3) {
  u64 v = f2mul(gy0, rv[i]);
  v = f2fma(gy1, rv[i + 1], v);
  v = f2fma(gy2, rv[i + 2], v);
  v = f2fma(gy3, rv[i + 3], v);
  v = f2fma(gy2, rv[i + 4], v);
  v = f2fma(gy1, rv[i + 5], v);
  v = f2fma(gy0, rv[i + 6], v);
  return v;
}

__device__ __forceinline__ void decode_shift(int si, int& sx, int& sy) {
  int t = si < 55 ? si : si + 1;   // skip (0,0) at index 55
  int q = t / 10;                  // x outer, y inner (matches reference)
  sx = q - 5;
  sy = t - q * 10 - 5;
}

extern "C" __global__ void __launch_bounds__(NTHREADS, 2)
mind_main(const float* __restrict__ pred, const float* __restrict__ gt) {
  extern __shared__ u64 smem[];
  u64* sImg = smem;
  u64* buf[2] = {smem + RH * IP2, smem + RH * IP2 + CHP * RP2};

  const int tX = blockIdx.x, tY = blockIdx.y, b = blockIdx.z;
  const int tid = threadIdx.x;
  const float* imgP = pred + b * HIMG * WIMG;
  const float* imgG = gt + b * HIMG * WIMG;

  // Load tile + halo (circular wrap), interleaving P/G into float2.
  float2* sImgF = (float2*)sImg;
  for (int i = tid; i < RH * RW; i += NTHREADS) {
    int r = i / RW, c2 = i - r * RW;
    int gr = tY * TILE_H + r; if (gr >= HIMG) gr -= HIMG;
    int gc = tX * TILE_W + c2; if (gc >= WIMG) gc -= WIMG;
    sImgF[r * IP2 + c2] = make_float2(imgP[gr * WIMG + gc],
                                      imgG[gr * WIMG + gc]);
  }
  __syncthreads();

  const int cc = tid & 63;   // owned output column within tile
  const int gg = tid >> 6;   // owned row-group (8 rows each)
  const u64 gy0 = bc2(GY0), gy1 = bc2(GY1), gy2 = bc2(GY2), gy3 = bc2(GY3);

  float DminP[8], DminG[8], VP[8], VG[8];
#pragma unroll
  for (int i = 0; i < 8; i++) {
    DminP[i] = 3e38f; DminG[i] = 3e38f; VP[i] = 0.f; VG[i] = 0.f;
  }

  int sx, sy;

  // ---------------- Pass A: Dmin and cardinal sum -> invV ----------------
  decode_shift(0, sx, sy);
  row_stage(sImg, buf[0], sx, sy, tid);
  __syncthreads();
  for (int si = 0; si < 99; si++) {
    int cur = si & 1;
    u64 rv[14];
    col_load(buf[cur], cc, gg, rv);
    decode_shift(si, sx, sy);
    bool card = ((sx == 0) & ((sy == 1) | (sy == -1))) |
                ((sy == 0) & ((sx == 1) | (sx == -1)));
#pragma unroll
    for (int i = 0; i < 8; i++) {
      u64 D2 = col7(rv, i, gy0, gy1, gy2, gy3);
      float dp, dg; up2(D2, dp, dg);
      DminP[i] = fminf(DminP[i], dp);
      DminG[i] = fminf(DminG[i], dg);
      if (card) { VP[i] += dp; VG[i] += dg; }
    }
    if (si + 1 < 99) {   // produce next shift into the other buffer
      int nsx, nsy;
      decode_shift(si + 1, nsx, nsy);
      row_stage(sImg, buf[cur ^ 1], nsx, nsy, tid);
    }
    __syncthreads();
  }
  u64 Dmin2[8], invV2[8];
#pragma unroll
  for (int i = 0; i < 8; i++) {
    Dmin2[i] = pk2(DminP[i], DminG[i]);
    invV2[i] = pk2(1.0f / (VP[i] * 0.25f + 1e-5f),
                   1.0f / (VG[i] * 0.25f + 1e-5f));
  }

  // ---------------- Pass B: accumulate |Mp - Mg| ----------------
  float acc = 0.f;
  const bool cOK = (tX * TILE_W + cc) < INNER;
  const int py0 = tY * TILE_H + gg * 8;

  decode_shift(0, sx, sy);
  row_stage(sImg, buf[0], sx, sy, tid);
  __syncthreads();
  for (int si = 0; si < 99; si++) {
    int cur = si & 1;
    u64 rv[14];
    col_load(buf[cur], cc, gg, rv);
#pragma unroll
    for (int i = 0; i < 8; i++) {
      u64 D2 = col7(rv, i, gy0, gy1, gy2, gy3);
      u64 e2 = f2mul(f2sub(Dmin2[i], D2), invV2[i]);
      float ep, eg; up2(e2, ep, eg);
      float mp = __expf(ep);
      float mg = __expf(eg);
      if (cOK && (py0 + i) < INNER) acc += fabsf(mp - mg);
    }
    if (si + 1 < 99) {
      int nsx, nsy;
      decode_shift(si + 1, nsx, nsy);
      row_stage(sImg, buf[cur ^ 1], nsx, nsy, tid);
    }
    __syncthreads();
  }

  // Deterministic per-CTA reduction.
#pragma unroll
  for (int o = 16; o > 0; o >>= 1) acc += __shfl_down_sync(0xffffffffu, acc, o);
  float* red = (float*)smem;   // passes done; safe reuse
  if ((tid & 31) == 0) red[tid >> 5] = acc;
  __syncthreads();
  if (tid == 0) {
    float s = 0.f;
#pragma unroll
    for (int w = 0; w < NTHREADS / 32; w++) s += red[w];
    g_partials[(b * TILES_Y + tY) * TILES_X + tX] = s;
  }
}

extern "C" __global__ void mind_reduce(float* __restrict__ out) {
  int tid = threadIdx.x;
  float s = 0.f;
  for (int i = tid; i < NCTAS; i += 256) s += g_partials[i];
#pragma unroll
  for (int o = 16; o > 0; o >>= 1) s += __shfl_down_sync(0xffffffffu, s, o);
  __shared__ float red[8];
  if ((tid & 31) == 0) red[tid >> 5] = s;
  __syncthreads();
  if (tid == 0) {
    float t = 0.f;
#pragma unroll
    for (int w = 0; w < 8; w++) t += red[w];
    out[0] = t * (float)(1.0 / ((double)BATCH * INNER * INNER * 99.0));
  }
}

extern "C" void kernel_launch(void* const* d_in, const int* in_sizes, int n_in,
                              void* d_out, int out_size) {
  const float* pred = (const float*)d_in[0];
  const float* gt = (const float*)d_in[1];
  cudaFuncSetAttribute(mind_main, cudaFuncAttributeMaxDynamicSharedMemorySize,
                       SMEM_BYTES);
  dim3 grid(TILES_X, TILES_Y, BATCH);
  mind_main<<<grid, NTHREADS, SMEM_BYTES>>>(pred, gt);
  mind_reduce<<<1, 256>>>((float*)d_out);
}